// round 12
// baseline (speedup 1.0000x reference)
#include <cuda_runtime.h>
#include <math.h>
#include <stdint.h>

#define N_NODES  262144
#define N_SEG    1024
#define N_HEADS  4
#define HID      64
#define DIM      512
#define NCOLS    256   // N_HEADS * HID

// ---------------- scratch (device globals; no allocations allowed) -------------
__device__ int   g_batch_step;
__device__ int   g_seg_start[N_SEG + 1];
__device__ float g_scores[N_NODES * N_HEADS];
__device__ float g_weights[N_NODES * N_HEADS];
__device__ float g_pooled[N_SEG * N_HEADS * DIM];
__device__ unsigned short g_whh[NCOLS * DIM];      // Wh pre-converted to fp16

// ---------------- helpers -------------------------------------------------------
__device__ __forceinline__ uint32_t smem_u32(const void* p) {
    uint32_t a;
    asm("{ .reg .u64 t; cvta.to.shared.u64 t, %1; cvt.u32.u64 %0, t; }" : "=r"(a) : "l"(p));
    return a;
}
__device__ __forceinline__ unsigned f2tf32(float f) {
    unsigned r;
    asm("cvt.rna.tf32.f32 %0, %1;" : "=r"(r) : "f"(f));
    return r;
}
// pack {lo, hi} as two rne fp16 in one b32
__device__ __forceinline__ unsigned pack_h2(float lo, float hi) {
    unsigned r;
    asm("cvt.rn.f16x2.f32 %0, %1, %2;" : "=r"(r) : "f"(hi), "f"(lo));
    return r;
}
__device__ __forceinline__ void cp16(uint32_t dst, const void* src) {
    asm volatile("cp.async.ca.shared.global [%0], [%1], 16;" :: "r"(dst), "l"(src));
}
#define CP_COMMIT() asm volatile("cp.async.commit_group;" ::: "memory")
#define CP_WAIT1()  asm volatile("cp.async.wait_group 1;" ::: "memory")

// ---------------- kernel 0: detect batch dtype ---------------------------------
__global__ void detect_kernel(const int* __restrict__ w) {
    g_batch_step = (w[N_NODES - 1] == 0) ? 2 : 1;
}

// ---------------- kernel 0b: convert Wh to fp16 (rne) --------------------------
__global__ void whconv_kernel(const float* __restrict__ Wh) {
    int idx = blockIdx.x * blockDim.x + threadIdx.x;   // 32768 float4 total
    float4 v = *(const float4*)(Wh + (size_t)idx * 4);
    uint2 u;
    u.x = pack_h2(v.x, v.y);
    u.y = pack_h2(v.z, v.w);
    *(uint2*)(g_whh + (size_t)idx * 4) = u;
}

// ---------------- kernel 1: segment boundaries (batch is sorted) ---------------
__global__ void seg_bounds_kernel(const int* __restrict__ w) {
    int n = blockIdx.x * blockDim.x + threadIdx.x;
    if (n >= N_NODES) return;
    const int step = g_batch_step;
    int b  = w[(size_t)n * step];
    int bp = (n == 0) ? -1 : w[(size_t)(n - 1) * step];
    b  = min(max(b, 0), N_SEG - 1);
    bp = min(max(bp, -1), N_SEG - 1);
    for (int s = bp + 1; s <= b; ++s) g_seg_start[s] = n;
    if (n == N_NODES - 1) {
        for (int s = b + 1; s <= N_SEG; ++s) g_seg_start[s] = N_NODES;
    }
}

// ---------------- kernel 2: fused scores GEMM (all-cp.async, fp16 mma, BK=64) --
// CTA tile 128x256, 256 threads (8 warps 2x4), warp tile 64x64.
// A: fp32 via cp.async, 3 stages, cvt->fp16 after LDS.64 (pack_h2).
// B: fp16 (g_whh) via cp.async, 3 stages. ONE __syncthreads per chunk:
// at iter kt, stage (kt+2)%3 was last read at kt-1 -> safe to refill after sync.
#define BM    128
#define BK    64
#define ROWA  72    // fp32 words per A row (64 + 8 pad): LDS.64 banks (8g+2t) OK
#define ROWB  36    // words per B row (64 fp16 + pad): banks (4c0+t) all-distinct
#define A_STAGE_BYTES (BM * ROWA * 4)      // 36864
#define B_STAGE_BYTES (NCOLS * ROWB * 4)   // 36864
#define B_BASE_OFF    (3 * A_STAGE_BYTES)  // 110592
#define SC_DYN (B_BASE_OFF + 3 * B_STAGE_BYTES)   // 221184 bytes

__global__ void __launch_bounds__(256, 1) scores_kernel(
    const float* __restrict__ x,
    const float* __restrict__ bh, const float* __restrict__ ctx)
{
    extern __shared__ float sh[];
    char* const shc = (char*)sh;
    const uint32_t shb = smem_u32(sh);

    const int tid  = threadIdx.x;
    const int lane = tid & 31;
    const int warp = tid >> 5;
    const int wm   = warp >> 2;   // 0..1
    const int wn   = warp & 3;    // 0..3 == head
    const int g    = lane >> 2;
    const int t    = lane & 3;

    const int bm0 = blockIdx.x * BM;

    // A: 128 rows x 16 float4-slots = 2048 / 256 thr = 8 each
    int aRow[8], aC4[8];
#pragma unroll
    for (int i = 0; i < 8; ++i) { int idx = tid + i * 256; aRow[i] = idx >> 4; aC4[i] = idx & 15; }
    // B: 256 rows x 8 cp-slots (16B = 8 fp16) = 2048 / 256 thr = 8 each
    int bRow[8], bC8[8];
#pragma unroll
    for (int i = 0; i < 8; ++i) { int idx = tid + i * 256; bRow[i] = idx >> 3; bC8[i] = idx & 7; }

#define SC_ISSUE(stage, kk)                                                          \
    do {                                                                             \
        uint32_t aB = shb + (stage) * A_STAGE_BYTES;                                 \
        uint32_t bB = shb + B_BASE_OFF + (stage) * B_STAGE_BYTES;                    \
        _Pragma("unroll")                                                            \
        for (int i = 0; i < 8; ++i)                                                  \
            cp16(aB + (aRow[i] * ROWA + aC4[i] * 4) * 4,                             \
                 x + (size_t)(bm0 + aRow[i]) * DIM + (kk) + aC4[i] * 4);             \
        _Pragma("unroll")                                                            \
        for (int i = 0; i < 8; ++i)                                                  \
            cp16(bB + (bRow[i] * ROWB + bC8[i] * 4) * 4,                             \
                 g_whh + (size_t)bRow[i] * DIM + (kk) + bC8[i] * 8);                 \
        CP_COMMIT();                                                                 \
    } while (0)

    // prologue: 2 chunks in flight
    SC_ISSUE(0, 0);
    SC_ISSUE(1, BK);

    float acc[4][8][4];
#pragma unroll
    for (int i = 0; i < 4; ++i)
#pragma unroll
        for (int j = 0; j < 8; ++j)
#pragma unroll
            for (int k = 0; k < 4; ++k) acc[i][j][k] = 0.f;

    const int NKT = DIM / BK;   // 8
    for (int kt = 0; kt < NKT; ++kt) {
        CP_WAIT1();
        __syncthreads();
        if (kt + 2 < NKT) SC_ISSUE((kt + 2) % 3, (kt + 2) * BK);
        const float*    aP = (const float*)(shc + (kt % 3) * A_STAGE_BYTES);
        const unsigned* bP = (const unsigned*)(shc + B_BASE_OFF + (kt % 3) * B_STAGE_BYTES);
#pragma unroll
        for (int ks = 0; ks < 4; ++ks) {           // four k16 steps per BK=64 chunk
            unsigned a[4][4], b[8][2];
#pragma unroll
            for (int mi = 0; mi < 4; ++mi) {
                int r0 = wm * 64 + mi * 16 + g;
                const float* p0 = aP + r0 * ROWA + ks * 16 + 2 * t;
                const float* p1 = aP + (r0 + 8) * ROWA + ks * 16 + 2 * t;
                float2 v00 = *(const float2*)(p0);
                float2 v10 = *(const float2*)(p1);
                float2 v01 = *(const float2*)(p0 + 8);
                float2 v11 = *(const float2*)(p1 + 8);
                a[mi][0] = pack_h2(v00.x, v00.y);
                a[mi][1] = pack_h2(v10.x, v10.y);
                a[mi][2] = pack_h2(v01.x, v01.y);
                a[mi][3] = pack_h2(v11.x, v11.y);
            }
#pragma unroll
            for (int ni = 0; ni < 8; ++ni) {
                int c0 = wn * 64 + ni * 8 + g;
                const unsigned* p = bP + c0 * ROWB + ks * 8 + t;
                b[ni][0] = p[0];
                b[ni][1] = p[4];
            }
#pragma unroll
            for (int mi = 0; mi < 4; ++mi)
#pragma unroll
                for (int ni = 0; ni < 8; ++ni) {
                    asm volatile(
                        "mma.sync.aligned.m16n8k16.row.col.f32.f16.f16.f32 "
                        "{%0,%1,%2,%3}, {%4,%5,%6,%7}, {%8,%9}, {%0,%1,%2,%3};\n"
                        : "+f"(acc[mi][ni][0]), "+f"(acc[mi][ni][1]),
                          "+f"(acc[mi][ni][2]), "+f"(acc[mi][ni][3])
                        : "r"(a[mi][0]), "r"(a[mi][1]), "r"(a[mi][2]), "r"(a[mi][3]),
                          "r"(b[ni][0]), "r"(b[ni][1]));
                }
        }
    }

    // fused epilogue: tanh + ctx dot, reduce this warp's 64 head-cols
    const int h = wn;
    const float* bhh  = bh  + h * HID;
    const float* ctxh = ctx + h * HID;
    float rs[4][2];
#pragma unroll
    for (int mi = 0; mi < 4; ++mi) { rs[mi][0] = 0.f; rs[mi][1] = 0.f; }

#pragma unroll
    for (int ni = 0; ni < 8; ++ni) {
        int k0 = ni * 8 + 2 * t;
        float bb0 = bhh[k0],  bb1 = bhh[k0 + 1];
        float cc0 = ctxh[k0], cc1 = ctxh[k0 + 1];
#pragma unroll
        for (int mi = 0; mi < 4; ++mi) {
            rs[mi][0] += tanhf(acc[mi][ni][0] + bb0) * cc0
                       + tanhf(acc[mi][ni][1] + bb1) * cc1;
            rs[mi][1] += tanhf(acc[mi][ni][2] + bb0) * cc0
                       + tanhf(acc[mi][ni][3] + bb1) * cc1;
        }
    }
#pragma unroll
    for (int mi = 0; mi < 4; ++mi)
#pragma unroll
        for (int rsel = 0; rsel < 2; ++rsel) {
            float v = rs[mi][rsel];
            v += __shfl_xor_sync(0xffffffffu, v, 1);
            v += __shfl_xor_sync(0xffffffffu, v, 2);
            if (t == 0) {
                int row = bm0 + wm * 64 + mi * 16 + g + rsel * 8;
                g_scores[row * 4 + h] = v;
            }
        }
}

// ---------------- kernel 3: per-segment softmax ---------------------------------
__device__ __forceinline__ float blk_max(float v, volatile float* red) {
#pragma unroll
    for (int o = 16; o; o >>= 1) v = fmaxf(v, __shfl_xor_sync(0xffffffffu, v, o));
    int w = threadIdx.x >> 5;
    if ((threadIdx.x & 31) == 0) red[w] = v;
    __syncthreads();
    float r = red[0];
#pragma unroll
    for (int i = 1; i < 8; ++i) r = fmaxf(r, red[i]);
    __syncthreads();
    return r;
}
__device__ __forceinline__ float blk_sum(float v, volatile float* red) {
#pragma unroll
    for (int o = 16; o; o >>= 1) v += __shfl_xor_sync(0xffffffffu, v, o);
    int w = threadIdx.x >> 5;
    if ((threadIdx.x & 31) == 0) red[w] = v;
    __syncthreads();
    float r = red[0];
#pragma unroll
    for (int i = 1; i < 8; ++i) r += red[i];
    __syncthreads();
    return r;
}

__global__ void __launch_bounds__(256) softmax_kernel() {
    __shared__ float red[8];
    const int b  = blockIdx.x;
    const int s0 = g_seg_start[b];
    const int s1 = g_seg_start[b + 1];
    const int tid = threadIdx.x;

    float m0 = -1e30f, m1 = -1e30f, m2 = -1e30f, m3 = -1e30f;
    for (int n = s0 + tid; n < s1; n += 256) {
        float4 s = *(const float4*)(g_scores + (size_t)n * 4);
        m0 = fmaxf(m0, s.x); m1 = fmaxf(m1, s.y);
        m2 = fmaxf(m2, s.z); m3 = fmaxf(m3, s.w);
    }
    float bm0 = blk_max(m0, red), bm1 = blk_max(m1, red);
    float bm2 = blk_max(m2, red), bm3 = blk_max(m3, red);

    float a0 = 0.f, a1 = 0.f, a2 = 0.f, a3 = 0.f;
    for (int n = s0 + tid; n < s1; n += 256) {
        float4 s = *(const float4*)(g_scores + (size_t)n * 4);
        a0 += expf(s.x - bm0); a1 += expf(s.y - bm1);
        a2 += expf(s.z - bm2); a3 += expf(s.w - bm3);
    }
    float sum0 = blk_sum(a0, red), sum1 = blk_sum(a1, red);
    float sum2 = blk_sum(a2, red), sum3 = blk_sum(a3, red);
    float i0 = 1.f / sum0, i1 = 1.f / sum1, i2 = 1.f / sum2, i3 = 1.f / sum3;

    for (int n = s0 + tid; n < s1; n += 256) {
        float4 s = *(const float4*)(g_scores + (size_t)n * 4);
        float4 w;
        w.x = expf(s.x - bm0) * i0;
        w.y = expf(s.y - bm1) * i1;
        w.z = expf(s.z - bm2) * i2;
        w.w = expf(s.w - bm3) * i3;
        *(float4*)(g_weights + (size_t)n * 4) = w;
    }
}

// ---------------- kernel 4: weighted segment pooling (8 loads in flight) -------
__device__ __forceinline__ void pool_acc(
    float4& p0, float4& p1, float4& p2, float4& p3,
    const float4 xv, const float4 wv)
{
    p0.x += wv.x * xv.x; p0.y += wv.x * xv.y; p0.z += wv.x * xv.z; p0.w += wv.x * xv.w;
    p1.x += wv.y * xv.x; p1.y += wv.y * xv.y; p1.z += wv.y * xv.z; p1.w += wv.y * xv.w;
    p2.x += wv.z * xv.x; p2.y += wv.z * xv.y; p2.z += wv.z * xv.z; p2.w += wv.z * xv.w;
    p3.x += wv.w * xv.x; p3.y += wv.w * xv.y; p3.z += wv.w * xv.z; p3.w += wv.w * xv.w;
}

__global__ void __launch_bounds__(512) pool_kernel(const float* __restrict__ x) {
    __shared__ __align__(16) float4 ws[64];
    __shared__ __align__(16) float4 part[4][128][4];

    const int b   = blockIdx.x;
    const int s0  = g_seg_start[b];
    const int s1  = g_seg_start[b + 1];
    const int tid = threadIdx.x;
    const int c   = tid & 127;
    const int r   = tid >> 7;

    float4 p0 = {0,0,0,0}, p1 = {0,0,0,0}, p2 = {0,0,0,0}, p3 = {0,0,0,0};

    for (int n0 = s0; n0 < s1; n0 += 64) {
        int cnt = min(64, s1 - n0);
        __syncthreads();
        if (tid < 64 && tid < cnt) ws[tid] = *(const float4*)(g_weights + (size_t)(n0 + tid) * 4);
        __syncthreads();
        const float* xb = x + (size_t)n0 * DIM + c * 4;
        int i = r;
        for (; i + 28 < cnt; i += 32) {
            float4 x0 = *(const float4*)(xb + (size_t)i * DIM);
            float4 x1 = *(const float4*)(xb + (size_t)(i + 4) * DIM);
            float4 x2 = *(const float4*)(xb + (size_t)(i + 8) * DIM);
            float4 x3 = *(const float4*)(xb + (size_t)(i + 12) * DIM);
            float4 x4 = *(const float4*)(xb + (size_t)(i + 16) * DIM);
            float4 x5 = *(const float4*)(xb + (size_t)(i + 20) * DIM);
            float4 x6 = *(const float4*)(xb + (size_t)(i + 24) * DIM);
            float4 x7 = *(const float4*)(xb + (size_t)(i + 28) * DIM);
            pool_acc(p0, p1, p2, p3, x0, ws[i]);
            pool_acc(p0, p1, p2, p3, x1, ws[i + 4]);
            pool_acc(p0, p1, p2, p3, x2, ws[i + 8]);
            pool_acc(p0, p1, p2, p3, x3, ws[i + 12]);
            pool_acc(p0, p1, p2, p3, x4, ws[i + 16]);
            pool_acc(p0, p1, p2, p3, x5, ws[i + 20]);
            pool_acc(p0, p1, p2, p3, x6, ws[i + 24]);
            pool_acc(p0, p1, p2, p3, x7, ws[i + 28]);
        }
        for (; i < cnt; i += 4) {
            float4 xv = *(const float4*)(xb + (size_t)i * DIM);
            pool_acc(p0, p1, p2, p3, xv, ws[i]);
        }
    }
    __syncthreads();
    part[r][c][0] = p0; part[r][c][1] = p1; part[r][c][2] = p2; part[r][c][3] = p3;
    __syncthreads();

    const int cc = tid & 127;
    const int h  = tid >> 7;
    float4 a = part[0][cc][h], b1 = part[1][cc][h], b2 = part[2][cc][h], b3 = part[3][cc][h];
    float4 o;
    o.x = a.x + b1.x + b2.x + b3.x;
    o.y = a.y + b1.y + b2.y + b3.y;
    o.z = a.z + b1.z + b2.z + b3.z;
    o.w = a.w + b1.w + b2.w + b3.w;
    *(float4*)(g_pooled + (size_t)b * (N_HEADS * DIM) + h * DIM + cc * 4) = o;
}

// ---------------- kernel 5: final GEMM (tf32 mma.sync, pipelined) --------------
#define SPAD 36
#define SKBK 32
#define FG_BM 64
#define FG_BN 64
#define FG_K  2048

__global__ void __launch_bounds__(128) final_gemm_kernel(
    const float* __restrict__ Wc, const float* __restrict__ bc,
    float* __restrict__ out)
{
    __shared__ __align__(16) unsigned As2[2][FG_BM][SPAD];
    __shared__ __align__(16) unsigned Bs2[2][FG_BN][SPAD];

    const int tid  = threadIdx.x;
    const int lane = tid & 31;
    const int warp = tid >> 5;
    const int wm   = warp >> 1;
    const int wn   = warp & 1;
    const int g    = lane >> 2;
    const int t    = lane & 3;

    const int bm = (blockIdx.x & 15) * FG_BM;
    const int bn = (blockIdx.x >> 4) * FG_BN;

    int ldRow[4], ldC4[4];
#pragma unroll
    for (int i = 0; i < 4; ++i) { int idx = tid + i * 128; ldRow[i] = idx >> 3; ldC4[i] = idx & 7; }

    float4 pa[4], pb[4];

#define FG_LOAD(kk)                                                                  \
    do {                                                                             \
        _Pragma("unroll")                                                            \
        for (int i = 0; i < 4; ++i) {                                                \
            pa[i] = *(const float4*)(g_pooled + (size_t)(bm + ldRow[i]) * FG_K + (kk) + ldC4[i] * 4); \
            pb[i] = *(const float4*)(Wc       + (size_t)(bn + ldRow[i]) * FG_K + (kk) + ldC4[i] * 4); \
        }                                                                            \
    } while (0)

#define FG_STORE(stage)                                                              \
    do {                                                                             \
        _Pragma("unroll")                                                            \
        for (int i = 0; i < 4; ++i) {                                                \
            uint4 va; va.x = f2tf32(pa[i].x); va.y = f2tf32(pa[i].y);                \
            va.z = f2tf32(pa[i].z); va.w = f2tf32(pa[i].w);                          \
            *(uint4*)&As2[stage][ldRow[i]][ldC4[i] * 4] = va;                        \
            uint4 vb; vb.x = f2tf32(pb[i].x); vb.y = f2tf32(pb[i].y);                \
            vb.z = f2tf32(pb[i].z); vb.w = f2tf32(pb[i].w);                          \
            *(uint4*)&Bs2[stage][ldRow[i]][ldC4[i] * 4] = vb;                        \
        }                                                                            \
    } while (0)

    FG_LOAD(0);
    FG_STORE(0);
    __syncthreads();

    float acc[2][4][4];
#pragma unroll
    for (int i = 0; i < 2; ++i)
#pragma unroll
        for (int j = 0; j < 4; ++j)
#pragma unroll
            for (int k = 0; k < 4; ++k) acc[i][j][k] = 0.f;

    const int NKT = FG_K / SKBK;
    for (int kt = 0; kt < NKT; ++kt) {
        const int s = kt & 1;
        if (kt < NKT - 1) FG_LOAD((kt + 1) * SKBK);
#pragma unroll
        for (int ks = 0; ks < 4; ++ks) {
            unsigned a[2][4], b[4][2];
#pragma unroll
            for (int mi = 0; mi < 2; ++mi) {
                int r0 = wm * 32 + mi * 16 + g;
                a[mi][0] = As2[s][r0    ][ks * 8 + t];
                a[mi][1] = As2[s][r0 + 8][ks * 8 + t];
                a[mi][2] = As2[s][r0    ][ks * 8 + t + 4];
                a[mi][3] = As2[s][r0 + 8][ks * 8 + t + 4];
            }
#pragma unroll
            for (int ni = 0; ni < 4; ++ni) {
                int c0 = wn * 32 + ni * 8 + g;
                b[ni][0] = Bs2[s][c0][ks * 8 + t];
                b[ni][1] = Bs2[s][c0][ks * 8 + t + 4];
            }
#pragma unroll
            for (int mi = 0; mi < 2; ++mi)
#pragma unroll
                for (int ni = 0; ni < 4; ++ni) {
                    asm volatile(
                        "mma.sync.aligned.m16n8k8.row.col.f32.tf32.tf32.f32 "
                        "{%0,%1,%2,%3}, {%4,%5,%6,%7}, {%8,%9}, {%0,%1,%2,%3};\n"
                        : "+f"(acc[mi][ni][0]), "+f"(acc[mi][ni][1]),
                          "+f"(acc[mi][ni][2]), "+f"(acc[mi][ni][3])
                        : "r"(a[mi][0]), "r"(a[mi][1]), "r"(a[mi][2]), "r"(a[mi][3]),
                          "r"(b[ni][0]), "r"(b[ni][1]));
                }
        }
        if (kt < NKT - 1) {
            FG_STORE(s ^ 1);
            __syncthreads();
        }
    }

#pragma unroll
    for (int mi = 0; mi < 2; ++mi)
#pragma unroll
        for (int ni = 0; ni < 4; ++ni) {
            int row0 = bm + wm * 32 + mi * 16 + g;
            int col0 = bn + wn * 32 + ni * 8 + 2 * t;
            out[(size_t)row0 * 512 + col0]           = acc[mi][ni][0] + bc[col0];
            out[(size_t)row0 * 512 + col0 + 1]       = acc[mi][ni][1] + bc[col0 + 1];
            out[(size_t)(row0 + 8) * 512 + col0]     = acc[mi][ni][2] + bc[col0];
            out[(size_t)(row0 + 8) * 512 + col0 + 1] = acc[mi][ni][3] + bc[col0 + 1];
        }
}

// ---------------- launcher -----------------------------------------------------
extern "C" void kernel_launch(void* const* d_in, const int* in_sizes, int n_in,
                              void* d_out, int out_size) {
    const float* x     = (const float*)d_in[0];
    const int*   batch = (const int*)d_in[1];
    const float* Wh    = (const float*)d_in[2];
    const float* bh    = (const float*)d_in[3];
    const float* ctx   = (const float*)d_in[4];
    const float* Wc    = (const float*)d_in[5];
    const float* bc    = (const float*)d_in[6];
    float*       out   = (float*)d_out;

    cudaFuncSetAttribute(scores_kernel,
                         cudaFuncAttributeMaxDynamicSharedMemorySize, SC_DYN);

    detect_kernel<<<1, 1>>>(batch);
    whconv_kernel<<<128, 256>>>(Wh);
    seg_bounds_kernel<<<N_NODES / 256, 256>>>(batch);
    scores_kernel<<<N_NODES / BM, 256, SC_DYN>>>(x, bh, ctx);   // launch #4: profiled
    softmax_kernel<<<N_SEG, 256>>>();
    pool_kernel<<<N_SEG, 512>>>(x);
    final_gemm_kernel<<<128, 128>>>(Wc, bc, out);
}

// round 13
// speedup vs baseline: 1.2400x; 1.2400x over previous
#include <cuda_runtime.h>
#include <math.h>
#include <stdint.h>

#define N_NODES  262144
#define N_SEG    1024
#define N_HEADS  4
#define HID      64
#define DIM      512
#define NCOLS    256   // N_HEADS * HID

// ---------------- scratch (device globals; no allocations allowed) -------------
__device__ int   g_batch_step;
__device__ int   g_seg_start[N_SEG + 1];
__device__ float g_scores[N_NODES * N_HEADS];
__device__ float g_weights[N_NODES * N_HEADS];
__device__ float g_pooled[N_SEG * N_HEADS * DIM];
__device__ unsigned short g_whh[NCOLS * DIM];      // Wh pre-converted to fp16
__device__ float g_fgpart[4][N_SEG * 512];         // split-K partials (8 MB)

// ---------------- helpers -------------------------------------------------------
__device__ __forceinline__ uint32_t smem_u32(const void* p) {
    uint32_t a;
    asm("{ .reg .u64 t; cvta.to.shared.u64 t, %1; cvt.u32.u64 %0, t; }" : "=r"(a) : "l"(p));
    return a;
}
__device__ __forceinline__ unsigned f2tf32(float f) {
    unsigned r;
    asm("cvt.rna.tf32.f32 %0, %1;" : "=r"(r) : "f"(f));
    return r;
}
// pack {lo, hi} as two rne fp16 in one b32
__device__ __forceinline__ unsigned pack_h2(float lo, float hi) {
    unsigned r;
    asm("cvt.rn.f16x2.f32 %0, %1, %2;" : "=r"(r) : "f"(hi), "f"(lo));
    return r;
}
__device__ __forceinline__ void cp16(uint32_t dst, const void* src) {
    asm volatile("cp.async.ca.shared.global [%0], [%1], 16;" :: "r"(dst), "l"(src));
}
#define CP_COMMIT() asm volatile("cp.async.commit_group;" ::: "memory")
#define CP_WAIT1()  asm volatile("cp.async.wait_group 1;" ::: "memory")

// ---------------- kernel 0: detect batch dtype ---------------------------------
__global__ void detect_kernel(const int* __restrict__ w) {
    g_batch_step = (w[N_NODES - 1] == 0) ? 2 : 1;
}

// ---------------- kernel 0b: convert Wh to fp16 (rne) --------------------------
__global__ void whconv_kernel(const float* __restrict__ Wh) {
    int idx = blockIdx.x * blockDim.x + threadIdx.x;   // 32768 float4 total
    float4 v = *(const float4*)(Wh + (size_t)idx * 4);
    uint2 u;
    u.x = pack_h2(v.x, v.y);
    u.y = pack_h2(v.z, v.w);
    *(uint2*)(g_whh + (size_t)idx * 4) = u;
}

// ---------------- kernel 1: segment boundaries (batch is sorted) ---------------
__global__ void seg_bounds_kernel(const int* __restrict__ w) {
    int n = blockIdx.x * blockDim.x + threadIdx.x;
    if (n >= N_NODES) return;
    const int step = g_batch_step;
    int b  = w[(size_t)n * step];
    int bp = (n == 0) ? -1 : w[(size_t)(n - 1) * step];
    b  = min(max(b, 0), N_SEG - 1);
    bp = min(max(bp, -1), N_SEG - 1);
    for (int s = bp + 1; s <= b; ++s) g_seg_start[s] = n;
    if (n == N_NODES - 1) {
        for (int s = b + 1; s <= N_SEG; ++s) g_seg_start[s] = N_NODES;
    }
}

// ---------------- kernel 2: fused scores GEMM (fp16 smem, fp16 mma, BK=64) -----
// (round-11 structure: A LDG->cvt->STS 2-stage, B cp.async fp16 2-stage)
#define BM    128
#define BK    64
#define ROWW  36
#define A_STAGE_BYTES (BM * ROWW * 4)      // 18432
#define B_STAGE_BYTES (NCOLS * ROWW * 4)   // 36864
#define B_BASE_OFF    (2 * A_STAGE_BYTES)  // 36864
#define SC_DYN (B_BASE_OFF + 2 * B_STAGE_BYTES)   // 110592 bytes

__global__ void __launch_bounds__(256, 1) scores_kernel(
    const float* __restrict__ x,
    const float* __restrict__ bh, const float* __restrict__ ctx)
{
    extern __shared__ float sh[];
    char* const shc = (char*)sh;
    const uint32_t shb = smem_u32(sh);

    const int tid  = threadIdx.x;
    const int lane = tid & 31;
    const int warp = tid >> 5;
    const int wm   = warp >> 2;   // 0..1
    const int wn   = warp & 3;    // 0..3 == head
    const int g    = lane >> 2;
    const int t    = lane & 3;

    const int bm0 = blockIdx.x * BM;

    int aRow[8], aC4[8];
#pragma unroll
    for (int i = 0; i < 8; ++i) { int idx = tid + i * 256; aRow[i] = idx >> 4; aC4[i] = idx & 15; }
    int bRow[8], bC8[8];
#pragma unroll
    for (int i = 0; i < 8; ++i) { int idx = tid + i * 256; bRow[i] = idx >> 3; bC8[i] = idx & 7; }

#define SC_ISSUE_B(stage, kk)                                                        \
    do {                                                                             \
        uint32_t bB = shb + B_BASE_OFF + (stage) * B_STAGE_BYTES;                    \
        _Pragma("unroll")                                                            \
        for (int i = 0; i < 8; ++i)                                                  \
            cp16(bB + (bRow[i] * ROWW + bC8[i] * 4) * 4,                             \
                 g_whh + (size_t)bRow[i] * DIM + (kk) + bC8[i] * 8);                 \
    } while (0)

#define SC_LDG_A(kk)                                                                 \
    do {                                                                             \
        _Pragma("unroll")                                                            \
        for (int i = 0; i < 8; ++i)                                                  \
            pa[i] = *(const float4*)(x + (size_t)(bm0 + aRow[i]) * DIM + (kk) + aC4[i] * 4); \
    } while (0)

#define SC_STS_A(stage)                                                              \
    do {                                                                             \
        uint32_t aB0 = (uint32_t)((stage) * A_STAGE_BYTES);                          \
        _Pragma("unroll")                                                            \
        for (int i = 0; i < 8; ++i) {                                                \
            uint2 u;                                                                 \
            u.x = pack_h2(pa[i].x, pa[i].y);                                         \
            u.y = pack_h2(pa[i].z, pa[i].w);                                         \
            *(uint2*)(shc + aB0 + (aRow[i] * ROWW + aC4[i] * 2) * 4) = u;            \
        }                                                                            \
    } while (0)

    float4 pa[8];

    SC_ISSUE_B(0, 0);  CP_COMMIT();
    SC_ISSUE_B(1, BK); CP_COMMIT();
    SC_LDG_A(0);
    SC_STS_A(0);

    float acc[4][8][4];
#pragma unroll
    for (int i = 0; i < 4; ++i)
#pragma unroll
        for (int j = 0; j < 8; ++j)
#pragma unroll
            for (int k = 0; k < 4; ++k) acc[i][j][k] = 0.f;

    const int NKT = DIM / BK;   // 8
    for (int kt = 0; kt < NKT; ++kt) {
        if (kt + 1 < NKT) SC_LDG_A((kt + 1) * BK);
        CP_WAIT1();
        __syncthreads();
        const char* aP = shc + (kt & 1) * A_STAGE_BYTES;
        const char* bP = shc + B_BASE_OFF + (kt & 1) * B_STAGE_BYTES;
#pragma unroll
        for (int ks = 0; ks < 4; ++ks) {
            unsigned a[4][4], b[8][2];
#pragma unroll
            for (int mi = 0; mi < 4; ++mi) {
                int r0 = wm * 64 + mi * 16 + g;
                const unsigned* p0 = (const unsigned*)(aP) + r0 * ROWW + ks * 8 + t;
                const unsigned* p1 = (const unsigned*)(aP) + (r0 + 8) * ROWW + ks * 8 + t;
                a[mi][0] = p0[0];
                a[mi][1] = p1[0];
                a[mi][2] = p0[4];
                a[mi][3] = p1[4];
            }
#pragma unroll
            for (int ni = 0; ni < 8; ++ni) {
                int c0 = wn * 64 + ni * 8 + g;
                const unsigned* p = (const unsigned*)(bP) + c0 * ROWW + ks * 8 + t;
                b[ni][0] = p[0];
                b[ni][1] = p[4];
            }
#pragma unroll
            for (int mi = 0; mi < 4; ++mi)
#pragma unroll
                for (int ni = 0; ni < 8; ++ni) {
                    asm volatile(
                        "mma.sync.aligned.m16n8k16.row.col.f32.f16.f16.f32 "
                        "{%0,%1,%2,%3}, {%4,%5,%6,%7}, {%8,%9}, {%0,%1,%2,%3};\n"
                        : "+f"(acc[mi][ni][0]), "+f"(acc[mi][ni][1]),
                          "+f"(acc[mi][ni][2]), "+f"(acc[mi][ni][3])
                        : "r"(a[mi][0]), "r"(a[mi][1]), "r"(a[mi][2]), "r"(a[mi][3]),
                          "r"(b[ni][0]), "r"(b[ni][1]));
                }
        }
        __syncthreads();
        if (kt + 1 < NKT) SC_STS_A((kt + 1) & 1);
        if (kt + 2 < NKT) SC_ISSUE_B((kt + 2) & 1, (kt + 2) * BK);
        CP_COMMIT();
    }

    // fused epilogue
    const int h = wn;
    const float* bhh  = bh  + h * HID;
    const float* ctxh = ctx + h * HID;
    float rs[4][2];
#pragma unroll
    for (int mi = 0; mi < 4; ++mi) { rs[mi][0] = 0.f; rs[mi][1] = 0.f; }

#pragma unroll
    for (int ni = 0; ni < 8; ++ni) {
        int k0 = ni * 8 + 2 * t;
        float bb0 = bhh[k0],  bb1 = bhh[k0 + 1];
        float cc0 = ctxh[k0], cc1 = ctxh[k0 + 1];
#pragma unroll
        for (int mi = 0; mi < 4; ++mi) {
            rs[mi][0] += tanhf(acc[mi][ni][0] + bb0) * cc0
                       + tanhf(acc[mi][ni][1] + bb1) * cc1;
            rs[mi][1] += tanhf(acc[mi][ni][2] + bb0) * cc0
                       + tanhf(acc[mi][ni][3] + bb1) * cc1;
        }
    }
#pragma unroll
    for (int mi = 0; mi < 4; ++mi)
#pragma unroll
        for (int rsel = 0; rsel < 2; ++rsel) {
            float v = rs[mi][rsel];
            v += __shfl_xor_sync(0xffffffffu, v, 1);
            v += __shfl_xor_sync(0xffffffffu, v, 2);
            if (t == 0) {
                int row = bm0 + wm * 64 + mi * 16 + g + rsel * 8;
                g_scores[row * 4 + h] = v;
            }
        }
}

// ---------------- kernel 3: per-segment softmax ---------------------------------
__device__ __forceinline__ float blk_max(float v, volatile float* red) {
#pragma unroll
    for (int o = 16; o; o >>= 1) v = fmaxf(v, __shfl_xor_sync(0xffffffffu, v, o));
    int w = threadIdx.x >> 5;
    if ((threadIdx.x & 31) == 0) red[w] = v;
    __syncthreads();
    float r = red[0];
#pragma unroll
    for (int i = 1; i < 8; ++i) r = fmaxf(r, red[i]);
    __syncthreads();
    return r;
}
__device__ __forceinline__ float blk_sum(float v, volatile float* red) {
#pragma unroll
    for (int o = 16; o; o >>= 1) v += __shfl_xor_sync(0xffffffffu, v, o);
    int w = threadIdx.x >> 5;
    if ((threadIdx.x & 31) == 0) red[w] = v;
    __syncthreads();
    float r = red[0];
#pragma unroll
    for (int i = 1; i < 8; ++i) r += red[i];
    __syncthreads();
    return r;
}

__global__ void __launch_bounds__(256) softmax_kernel() {
    __shared__ float red[8];
    const int b  = blockIdx.x;
    const int s0 = g_seg_start[b];
    const int s1 = g_seg_start[b + 1];
    const int tid = threadIdx.x;

    float m0 = -1e30f, m1 = -1e30f, m2 = -1e30f, m3 = -1e30f;
    for (int n = s0 + tid; n < s1; n += 256) {
        float4 s = *(const float4*)(g_scores + (size_t)n * 4);
        m0 = fmaxf(m0, s.x); m1 = fmaxf(m1, s.y);
        m2 = fmaxf(m2, s.z); m3 = fmaxf(m3, s.w);
    }
    float bm0 = blk_max(m0, red), bm1 = blk_max(m1, red);
    float bm2 = blk_max(m2, red), bm3 = blk_max(m3, red);

    float a0 = 0.f, a1 = 0.f, a2 = 0.f, a3 = 0.f;
    for (int n = s0 + tid; n < s1; n += 256) {
        float4 s = *(const float4*)(g_scores + (size_t)n * 4);
        a0 += expf(s.x - bm0); a1 += expf(s.y - bm1);
        a2 += expf(s.z - bm2); a3 += expf(s.w - bm3);
    }
    float sum0 = blk_sum(a0, red), sum1 = blk_sum(a1, red);
    float sum2 = blk_sum(a2, red), sum3 = blk_sum(a3, red);
    float i0 = 1.f / sum0, i1 = 1.f / sum1, i2 = 1.f / sum2, i3 = 1.f / sum3;

    for (int n = s0 + tid; n < s1; n += 256) {
        float4 s = *(const float4*)(g_scores + (size_t)n * 4);
        float4 w;
        w.x = expf(s.x - bm0) * i0;
        w.y = expf(s.y - bm1) * i1;
        w.z = expf(s.z - bm2) * i2;
        w.w = expf(s.w - bm3) * i3;
        *(float4*)(g_weights + (size_t)n * 4) = w;
    }
}

// ---------------- kernel 4: weighted segment pooling (8 loads in flight) -------
__device__ __forceinline__ void pool_acc(
    float4& p0, float4& p1, float4& p2, float4& p3,
    const float4 xv, const float4 wv)
{
    p0.x += wv.x * xv.x; p0.y += wv.x * xv.y; p0.z += wv.x * xv.z; p0.w += wv.x * xv.w;
    p1.x += wv.y * xv.x; p1.y += wv.y * xv.y; p1.z += wv.y * xv.z; p1.w += wv.y * xv.w;
    p2.x += wv.z * xv.x; p2.y += wv.z * xv.y; p2.z += wv.z * xv.z; p2.w += wv.z * xv.w;
    p3.x += wv.w * xv.x; p3.y += wv.w * xv.y; p3.z += wv.w * xv.z; p3.w += wv.w * xv.w;
}

__global__ void __launch_bounds__(512) pool_kernel(const float* __restrict__ x) {
    __shared__ __align__(16) float4 ws[64];
    __shared__ __align__(16) float4 part[4][128][4];

    const int b   = blockIdx.x;
    const int s0  = g_seg_start[b];
    const int s1  = g_seg_start[b + 1];
    const int tid = threadIdx.x;
    const int c   = tid & 127;
    const int r   = tid >> 7;

    float4 p0 = {0,0,0,0}, p1 = {0,0,0,0}, p2 = {0,0,0,0}, p3 = {0,0,0,0};

    for (int n0 = s0; n0 < s1; n0 += 64) {
        int cnt = min(64, s1 - n0);
        __syncthreads();
        if (tid < 64 && tid < cnt) ws[tid] = *(const float4*)(g_weights + (size_t)(n0 + tid) * 4);
        __syncthreads();
        const float* xb = x + (size_t)n0 * DIM + c * 4;
        int i = r;
        for (; i + 28 < cnt; i += 32) {
            float4 x0 = *(const float4*)(xb + (size_t)i * DIM);
            float4 x1 = *(const float4*)(xb + (size_t)(i + 4) * DIM);
            float4 x2 = *(const float4*)(xb + (size_t)(i + 8) * DIM);
            float4 x3 = *(const float4*)(xb + (size_t)(i + 12) * DIM);
            float4 x4 = *(const float4*)(xb + (size_t)(i + 16) * DIM);
            float4 x5 = *(const float4*)(xb + (size_t)(i + 20) * DIM);
            float4 x6 = *(const float4*)(xb + (size_t)(i + 24) * DIM);
            float4 x7 = *(const float4*)(xb + (size_t)(i + 28) * DIM);
            pool_acc(p0, p1, p2, p3, x0, ws[i]);
            pool_acc(p0, p1, p2, p3, x1, ws[i + 4]);
            pool_acc(p0, p1, p2, p3, x2, ws[i + 8]);
            pool_acc(p0, p1, p2, p3, x3, ws[i + 12]);
            pool_acc(p0, p1, p2, p3, x4, ws[i + 16]);
            pool_acc(p0, p1, p2, p3, x5, ws[i + 20]);
            pool_acc(p0, p1, p2, p3, x6, ws[i + 24]);
            pool_acc(p0, p1, p2, p3, x7, ws[i + 28]);
        }
        for (; i < cnt; i += 4) {
            float4 xv = *(const float4*)(xb + (size_t)i * DIM);
            pool_acc(p0, p1, p2, p3, xv, ws[i]);
        }
    }
    __syncthreads();
    part[r][c][0] = p0; part[r][c][1] = p1; part[r][c][2] = p2; part[r][c][3] = p3;
    __syncthreads();

    const int cc = tid & 127;
    const int h  = tid >> 7;
    float4 a = part[0][cc][h], b1 = part[1][cc][h], b2 = part[2][cc][h], b3 = part[3][cc][h];
    float4 o;
    o.x = a.x + b1.x + b2.x + b3.x;
    o.y = a.y + b1.y + b2.y + b3.y;
    o.z = a.z + b1.z + b2.z + b3.z;
    o.w = a.w + b1.w + b2.w + b3.w;
    *(float4*)(g_pooled + (size_t)b * (N_HEADS * DIM) + h * DIM + cc * 4) = o;
}

// ---------------- kernel 5: final GEMM, split-K=4 (tf32 mma.sync) --------------
// 512 CTAs = 16 M-blocks x 8 N-blocks x 4 K-slices; each computes 64x64 over K=512.
#define SPAD 36
#define SKBK 32
#define FG_BM 64
#define FG_BN 64
#define FG_K  2048
#define FG_KSPLIT 4
#define FG_KS (FG_K / FG_KSPLIT)   // 512

__global__ void __launch_bounds__(128) final_gemm_kernel(const float* __restrict__ Wc)
{
    __shared__ __align__(16) unsigned As2[2][FG_BM][SPAD];
    __shared__ __align__(16) unsigned Bs2[2][FG_BN][SPAD];

    const int tid  = threadIdx.x;
    const int lane = tid & 31;
    const int warp = tid >> 5;
    const int wm   = warp >> 1;
    const int wn   = warp & 1;
    const int g    = lane >> 2;
    const int t    = lane & 3;

    const int bm   = (blockIdx.x & 15) * FG_BM;          // 16 M-blocks
    const int bn   = ((blockIdx.x >> 4) & 7) * FG_BN;    // 8 N-blocks
    const int kq   = blockIdx.x >> 7;                    // 4 K-slices
    const int koff = kq * FG_KS;

    int ldRow[4], ldC4[4];
#pragma unroll
    for (int i = 0; i < 4; ++i) { int idx = tid + i * 128; ldRow[i] = idx >> 3; ldC4[i] = idx & 7; }

    float4 pa[4], pb[4];

#define FG_LOAD(kk)                                                                  \
    do {                                                                             \
        _Pragma("unroll")                                                            \
        for (int i = 0; i < 4; ++i) {                                                \
            pa[i] = *(const float4*)(g_pooled + (size_t)(bm + ldRow[i]) * FG_K + (kk) + ldC4[i] * 4); \
            pb[i] = *(const float4*)(Wc       + (size_t)(bn + ldRow[i]) * FG_K + (kk) + ldC4[i] * 4); \
        }                                                                            \
    } while (0)

#define FG_STORE(stage)                                                              \
    do {                                                                             \
        _Pragma("unroll")                                                            \
        for (int i = 0; i < 4; ++i) {                                                \
            uint4 va; va.x = f2tf32(pa[i].x); va.y = f2tf32(pa[i].y);                \
            va.z = f2tf32(pa[i].z); va.w = f2tf32(pa[i].w);                          \
            *(uint4*)&As2[stage][ldRow[i]][ldC4[i] * 4] = va;                        \
            uint4 vb; vb.x = f2tf32(pb[i].x); vb.y = f2tf32(pb[i].y);                \
            vb.z = f2tf32(pb[i].z); vb.w = f2tf32(pb[i].w);                          \
            *(uint4*)&Bs2[stage][ldRow[i]][ldC4[i] * 4] = vb;                        \
        }                                                                            \
    } while (0)

    FG_LOAD(koff);
    FG_STORE(0);
    __syncthreads();

    float acc[2][4][4];
#pragma unroll
    for (int i = 0; i < 2; ++i)
#pragma unroll
        for (int j = 0; j < 4; ++j)
#pragma unroll
            for (int k = 0; k < 4; ++k) acc[i][j][k] = 0.f;

    const int NKT = FG_KS / SKBK;   // 16
    for (int kt = 0; kt < NKT; ++kt) {
        const int s = kt & 1;
        if (kt < NKT - 1) FG_LOAD(koff + (kt + 1) * SKBK);
#pragma unroll
        for (int ks = 0; ks < 4; ++ks) {
            unsigned a[2][4], b[4][2];
#pragma unroll
            for (int mi = 0; mi < 2; ++mi) {
                int r0 = wm * 32 + mi * 16 + g;
                a[mi][0] = As2[s][r0    ][ks * 8 + t];
                a[mi][1] = As2[s][r0 + 8][ks * 8 + t];
                a[mi][2] = As2[s][r0    ][ks * 8 + t + 4];
                a[mi][3] = As2[s][r0 + 8][ks * 8 + t + 4];
            }
#pragma unroll
            for (int ni = 0; ni < 4; ++ni) {
                int c0 = wn * 32 + ni * 8 + g;
                b[ni][0] = Bs2[s][c0][ks * 8 + t];
                b[ni][1] = Bs2[s][c0][ks * 8 + t + 4];
            }
#pragma unroll
            for (int mi = 0; mi < 2; ++mi)
#pragma unroll
                for (int ni = 0; ni < 4; ++ni) {
                    asm volatile(
                        "mma.sync.aligned.m16n8k8.row.col.f32.tf32.tf32.f32 "
                        "{%0,%1,%2,%3}, {%4,%5,%6,%7}, {%8,%9}, {%0,%1,%2,%3};\n"
                        : "+f"(acc[mi][ni][0]), "+f"(acc[mi][ni][1]),
                          "+f"(acc[mi][ni][2]), "+f"(acc[mi][ni][3])
                        : "r"(a[mi][0]), "r"(a[mi][1]), "r"(a[mi][2]), "r"(a[mi][3]),
                          "r"(b[ni][0]), "r"(b[ni][1]));
                }
        }
        if (kt < NKT - 1) {
            FG_STORE(s ^ 1);
            __syncthreads();
        }
    }

    float* outp = g_fgpart[kq];
#pragma unroll
    for (int mi = 0; mi < 2; ++mi)
#pragma unroll
        for (int ni = 0; ni < 4; ++ni) {
            int row0 = bm + wm * 32 + mi * 16 + g;
            int col0 = bn + wn * 32 + ni * 8 + 2 * t;
            outp[(size_t)row0 * 512 + col0]           = acc[mi][ni][0];
            outp[(size_t)row0 * 512 + col0 + 1]       = acc[mi][ni][1];
            outp[(size_t)(row0 + 8) * 512 + col0]     = acc[mi][ni][2];
            outp[(size_t)(row0 + 8) * 512 + col0 + 1] = acc[mi][ni][3];
        }
}

// ---------------- kernel 6: split-K reduce + bias -------------------------------
__global__ void __launch_bounds__(256) fg_reduce_kernel(
    const float* __restrict__ bc, float* __restrict__ out)
{
    int idx4 = blockIdx.x * blockDim.x + threadIdx.x;   // 131072 float4
    float4 p0 = *(const float4*)(g_fgpart[0] + (size_t)idx4 * 4);
    float4 p1 = *(const float4*)(g_fgpart[1] + (size_t)idx4 * 4);
    float4 p2 = *(const float4*)(g_fgpart[2] + (size_t)idx4 * 4);
    float4 p3 = *(const float4*)(g_fgpart[3] + (size_t)idx4 * 4);
    int col = (idx4 * 4) & 511;
    float4 bb = *(const float4*)(bc + col);
    float4 o;
    o.x = p0.x + p1.x + p2.x + p3.x + bb.x;
    o.y = p0.y + p1.y + p2.y + p3.y + bb.y;
    o.z = p0.z + p1.z + p2.z + p3.z + bb.z;
    o.w = p0.w + p1.w + p2.w + p3.w + bb.w;
    *(float4*)(out + (size_t)idx4 * 4) = o;
}

// ---------------- launcher -----------------------------------------------------
extern "C" void kernel_launch(void* const* d_in, const int* in_sizes, int n_in,
                              void* d_out, int out_size) {
    const float* x     = (const float*)d_in[0];
    const int*   batch = (const int*)d_in[1];
    const float* Wh    = (const float*)d_in[2];
    const float* bh    = (const float*)d_in[3];
    const float* ctx   = (const float*)d_in[4];
    const float* Wc    = (const float*)d_in[5];
    const float* bc    = (const float*)d_in[6];
    float*       out   = (float*)d_out;

    cudaFuncSetAttribute(scores_kernel,
                         cudaFuncAttributeMaxDynamicSharedMemorySize, SC_DYN);

    detect_kernel<<<1, 1>>>(batch);
    whconv_kernel<<<128, 256>>>(Wh);
    seg_bounds_kernel<<<N_NODES / 256, 256>>>(batch);
    scores_kernel<<<N_NODES / BM, 256, SC_DYN>>>(x, bh, ctx);   // launch #4: profiled
    softmax_kernel<<<N_SEG, 256>>>();
    pool_kernel<<<N_SEG, 512>>>(x);
    final_gemm_kernel<<<512, 128>>>(Wc);
    fg_reduce_kernel<<<512, 256>>>(bc, out);
}

// round 14
// speedup vs baseline: 1.2533x; 1.0108x over previous
#include <cuda_runtime.h>
#include <math.h>
#include <stdint.h>

#define N_NODES  262144
#define N_SEG    1024
#define N_HEADS  4
#define HID      64
#define DIM      512
#define NCOLS    256   // N_HEADS * HID

// ---------------- scratch (device globals; no allocations allowed) -------------
__device__ int   g_batch_step;
__device__ int   g_seg_start[N_SEG + 1];
__device__ float g_scores[N_NODES * N_HEADS];
__device__ float g_weights[N_NODES * N_HEADS];
__device__ float g_pooled[N_SEG * N_HEADS * DIM];
__device__ unsigned short g_whh[NCOLS * DIM];      // Wh pre-converted to fp16
__device__ float g_fgpart[4][N_SEG * 512];         // split-K partials (8 MB)

// ---------------- helpers -------------------------------------------------------
__device__ __forceinline__ uint32_t smem_u32(const void* p) {
    uint32_t a;
    asm("{ .reg .u64 t; cvta.to.shared.u64 t, %1; cvt.u32.u64 %0, t; }" : "=r"(a) : "l"(p));
    return a;
}
__device__ __forceinline__ unsigned f2tf32(float f) {
    unsigned r;
    asm("cvt.rna.tf32.f32 %0, %1;" : "=r"(r) : "f"(f));
    return r;
}
// pack {lo, hi} as two rne fp16 in one b32
__device__ __forceinline__ unsigned pack_h2(float lo, float hi) {
    unsigned r;
    asm("cvt.rn.f16x2.f32 %0, %1, %2;" : "=r"(r) : "f"(hi), "f"(lo));
    return r;
}
__device__ __forceinline__ void cp16(uint32_t dst, const void* src) {
    asm volatile("cp.async.ca.shared.global [%0], [%1], 16;" :: "r"(dst), "l"(src));
}
#define CP_COMMIT() asm volatile("cp.async.commit_group;" ::: "memory")
#define CP_WAIT1()  asm volatile("cp.async.wait_group 1;" ::: "memory")

// ---------------- kernel 0: detect batch dtype ---------------------------------
__global__ void detect_kernel(const int* __restrict__ w) {
    g_batch_step = (w[N_NODES - 1] == 0) ? 2 : 1;
}

// ---------------- kernel 0b: convert Wh to fp16 (rne) --------------------------
__global__ void whconv_kernel(const float* __restrict__ Wh) {
    int idx = blockIdx.x * blockDim.x + threadIdx.x;   // 32768 float4 total
    float4 v = *(const float4*)(Wh + (size_t)idx * 4);
    uint2 u;
    u.x = pack_h2(v.x, v.y);
    u.y = pack_h2(v.z, v.w);
    *(uint2*)(g_whh + (size_t)idx * 4) = u;
}

// ---------------- kernel 1: segment boundaries (batch is sorted) ---------------
__global__ void seg_bounds_kernel(const int* __restrict__ w) {
    int n = blockIdx.x * blockDim.x + threadIdx.x;
    if (n >= N_NODES) return;
    const int step = g_batch_step;
    int b  = w[(size_t)n * step];
    int bp = (n == 0) ? -1 : w[(size_t)(n - 1) * step];
    b  = min(max(b, 0), N_SEG - 1);
    bp = min(max(bp, -1), N_SEG - 1);
    for (int s = bp + 1; s <= b; ++s) g_seg_start[s] = n;
    if (n == N_NODES - 1) {
        for (int s = b + 1; s <= N_SEG; ++s) g_seg_start[s] = N_NODES;
    }
}

// ---------------- kernel 2: fused scores GEMM (fp16 smem, fp16 mma, BK=64) -----
// (round-11 structure: A LDG->cvt->STS 2-stage, B cp.async fp16 2-stage)
#define BM    128
#define BK    64
#define ROWW  36
#define A_STAGE_BYTES (BM * ROWW * 4)      // 18432
#define B_STAGE_BYTES (NCOLS * ROWW * 4)   // 36864
#define B_BASE_OFF    (2 * A_STAGE_BYTES)  // 36864
#define SC_DYN (B_BASE_OFF + 2 * B_STAGE_BYTES)   // 110592 bytes

__global__ void __launch_bounds__(256, 1) scores_kernel(
    const float* __restrict__ x,
    const float* __restrict__ bh, const float* __restrict__ ctx)
{
    extern __shared__ float sh[];
    char* const shc = (char*)sh;
    const uint32_t shb = smem_u32(sh);

    const int tid  = threadIdx.x;
    const int lane = tid & 31;
    const int warp = tid >> 5;
    const int wm   = warp >> 2;   // 0..1
    const int wn   = warp & 3;    // 0..3 == head
    const int g    = lane >> 2;
    const int t    = lane & 3;

    const int bm0 = blockIdx.x * BM;

    int aRow[8], aC4[8];
#pragma unroll
    for (int i = 0; i < 8; ++i) { int idx = tid + i * 256; aRow[i] = idx >> 4; aC4[i] = idx & 15; }
    int bRow[8], bC8[8];
#pragma unroll
    for (int i = 0; i < 8; ++i) { int idx = tid + i * 256; bRow[i] = idx >> 3; bC8[i] = idx & 7; }

#define SC_ISSUE_B(stage, kk)                                                        \
    do {                                                                             \
        uint32_t bB = shb + B_BASE_OFF + (stage) * B_STAGE_BYTES;                    \
        _Pragma("unroll")                                                            \
        for (int i = 0; i < 8; ++i)                                                  \
            cp16(bB + (bRow[i] * ROWW + bC8[i] * 4) * 4,                             \
                 g_whh + (size_t)bRow[i] * DIM + (kk) + bC8[i] * 8);                 \
    } while (0)

#define SC_LDG_A(kk)                                                                 \
    do {                                                                             \
        _Pragma("unroll")                                                            \
        for (int i = 0; i < 8; ++i)                                                  \
            pa[i] = *(const float4*)(x + (size_t)(bm0 + aRow[i]) * DIM + (kk) + aC4[i] * 4); \
    } while (0)

#define SC_STS_A(stage)                                                              \
    do {                                                                             \
        uint32_t aB0 = (uint32_t)((stage) * A_STAGE_BYTES);                          \
        _Pragma("unroll")                                                            \
        for (int i = 0; i < 8; ++i) {                                                \
            uint2 u;                                                                 \
            u.x = pack_h2(pa[i].x, pa[i].y);                                         \
            u.y = pack_h2(pa[i].z, pa[i].w);                                         \
            *(uint2*)(shc + aB0 + (aRow[i] * ROWW + aC4[i] * 2) * 4) = u;            \
        }                                                                            \
    } while (0)

    float4 pa[8];

    SC_ISSUE_B(0, 0);  CP_COMMIT();
    SC_ISSUE_B(1, BK); CP_COMMIT();
    SC_LDG_A(0);
    SC_STS_A(0);

    float acc[4][8][4];
#pragma unroll
    for (int i = 0; i < 4; ++i)
#pragma unroll
        for (int j = 0; j < 8; ++j)
#pragma unroll
            for (int k = 0; k < 4; ++k) acc[i][j][k] = 0.f;

    const int NKT = DIM / BK;   // 8
    for (int kt = 0; kt < NKT; ++kt) {
        if (kt + 1 < NKT) SC_LDG_A((kt + 1) * BK);
        CP_WAIT1();
        __syncthreads();
        const char* aP = shc + (kt & 1) * A_STAGE_BYTES;
        const char* bP = shc + B_BASE_OFF + (kt & 1) * B_STAGE_BYTES;
#pragma unroll
        for (int ks = 0; ks < 4; ++ks) {
            unsigned a[4][4], b[8][2];
#pragma unroll
            for (int mi = 0; mi < 4; ++mi) {
                int r0 = wm * 64 + mi * 16 + g;
                const unsigned* p0 = (const unsigned*)(aP) + r0 * ROWW + ks * 8 + t;
                const unsigned* p1 = (const unsigned*)(aP) + (r0 + 8) * ROWW + ks * 8 + t;
                a[mi][0] = p0[0];
                a[mi][1] = p1[0];
                a[mi][2] = p0[4];
                a[mi][3] = p1[4];
            }
#pragma unroll
            for (int ni = 0; ni < 8; ++ni) {
                int c0 = wn * 64 + ni * 8 + g;
                const unsigned* p = (const unsigned*)(bP) + c0 * ROWW + ks * 8 + t;
                b[ni][0] = p[0];
                b[ni][1] = p[4];
            }
#pragma unroll
            for (int mi = 0; mi < 4; ++mi)
#pragma unroll
                for (int ni = 0; ni < 8; ++ni) {
                    asm volatile(
                        "mma.sync.aligned.m16n8k16.row.col.f32.f16.f16.f32 "
                        "{%0,%1,%2,%3}, {%4,%5,%6,%7}, {%8,%9}, {%0,%1,%2,%3};\n"
                        : "+f"(acc[mi][ni][0]), "+f"(acc[mi][ni][1]),
                          "+f"(acc[mi][ni][2]), "+f"(acc[mi][ni][3])
                        : "r"(a[mi][0]), "r"(a[mi][1]), "r"(a[mi][2]), "r"(a[mi][3]),
                          "r"(b[ni][0]), "r"(b[ni][1]));
                }
        }
        __syncthreads();
        if (kt + 1 < NKT) SC_STS_A((kt + 1) & 1);
        if (kt + 2 < NKT) SC_ISSUE_B((kt + 2) & 1, (kt + 2) * BK);
        CP_COMMIT();
    }

    // fused epilogue
    const int h = wn;
    const float* bhh  = bh  + h * HID;
    const float* ctxh = ctx + h * HID;
    float rs[4][2];
#pragma unroll
    for (int mi = 0; mi < 4; ++mi) { rs[mi][0] = 0.f; rs[mi][1] = 0.f; }

#pragma unroll
    for (int ni = 0; ni < 8; ++ni) {
        int k0 = ni * 8 + 2 * t;
        float bb0 = bhh[k0],  bb1 = bhh[k0 + 1];
        float cc0 = ctxh[k0], cc1 = ctxh[k0 + 1];
#pragma unroll
        for (int mi = 0; mi < 4; ++mi) {
            rs[mi][0] += tanhf(acc[mi][ni][0] + bb0) * cc0
                       + tanhf(acc[mi][ni][1] + bb1) * cc1;
            rs[mi][1] += tanhf(acc[mi][ni][2] + bb0) * cc0
                       + tanhf(acc[mi][ni][3] + bb1) * cc1;
        }
    }
#pragma unroll
    for (int mi = 0; mi < 4; ++mi)
#pragma unroll
        for (int rsel = 0; rsel < 2; ++rsel) {
            float v = rs[mi][rsel];
            v += __shfl_xor_sync(0xffffffffu, v, 1);
            v += __shfl_xor_sync(0xffffffffu, v, 2);
            if (t == 0) {
                int row = bm0 + wm * 64 + mi * 16 + g + rsel * 8;
                g_scores[row * 4 + h] = v;
            }
        }
}

// ---------------- kernel 3: per-segment softmax ---------------------------------
__device__ __forceinline__ float blk_max(float v, volatile float* red) {
#pragma unroll
    for (int o = 16; o; o >>= 1) v = fmaxf(v, __shfl_xor_sync(0xffffffffu, v, o));
    int w = threadIdx.x >> 5;
    if ((threadIdx.x & 31) == 0) red[w] = v;
    __syncthreads();
    float r = red[0];
#pragma unroll
    for (int i = 1; i < 8; ++i) r = fmaxf(r, red[i]);
    __syncthreads();
    return r;
}
__device__ __forceinline__ float blk_sum(float v, volatile float* red) {
#pragma unroll
    for (int o = 16; o; o >>= 1) v += __shfl_xor_sync(0xffffffffu, v, o);
    int w = threadIdx.x >> 5;
    if ((threadIdx.x & 31) == 0) red[w] = v;
    __syncthreads();
    float r = red[0];
#pragma unroll
    for (int i = 1; i < 8; ++i) r += red[i];
    __syncthreads();
    return r;
}

__global__ void __launch_bounds__(256) softmax_kernel() {
    __shared__ float red[8];
    const int b  = blockIdx.x;
    const int s0 = g_seg_start[b];
    const int s1 = g_seg_start[b + 1];
    const int tid = threadIdx.x;

    float m0 = -1e30f, m1 = -1e30f, m2 = -1e30f, m3 = -1e30f;
    for (int n = s0 + tid; n < s1; n += 256) {
        float4 s = *(const float4*)(g_scores + (size_t)n * 4);
        m0 = fmaxf(m0, s.x); m1 = fmaxf(m1, s.y);
        m2 = fmaxf(m2, s.z); m3 = fmaxf(m3, s.w);
    }
    float bm0 = blk_max(m0, red), bm1 = blk_max(m1, red);
    float bm2 = blk_max(m2, red), bm3 = blk_max(m3, red);

    float a0 = 0.f, a1 = 0.f, a2 = 0.f, a3 = 0.f;
    for (int n = s0 + tid; n < s1; n += 256) {
        float4 s = *(const float4*)(g_scores + (size_t)n * 4);
        a0 += expf(s.x - bm0); a1 += expf(s.y - bm1);
        a2 += expf(s.z - bm2); a3 += expf(s.w - bm3);
    }
    float sum0 = blk_sum(a0, red), sum1 = blk_sum(a1, red);
    float sum2 = blk_sum(a2, red), sum3 = blk_sum(a3, red);
    float i0 = 1.f / sum0, i1 = 1.f / sum1, i2 = 1.f / sum2, i3 = 1.f / sum3;

    for (int n = s0 + tid; n < s1; n += 256) {
        float4 s = *(const float4*)(g_scores + (size_t)n * 4);
        float4 w;
        w.x = expf(s.x - bm0) * i0;
        w.y = expf(s.y - bm1) * i1;
        w.z = expf(s.z - bm2) * i2;
        w.w = expf(s.w - bm3) * i3;
        *(float4*)(g_weights + (size_t)n * 4) = w;
    }
}

// ---------------- kernel 4: weighted segment pooling (8 loads in flight) -------
__device__ __forceinline__ void pool_acc(
    float4& p0, float4& p1, float4& p2, float4& p3,
    const float4 xv, const float4 wv)
{
    p0.x += wv.x * xv.x; p0.y += wv.x * xv.y; p0.z += wv.x * xv.z; p0.w += wv.x * xv.w;
    p1.x += wv.y * xv.x; p1.y += wv.y * xv.y; p1.z += wv.y * xv.z; p1.w += wv.y * xv.w;
    p2.x += wv.z * xv.x; p2.y += wv.z * xv.y; p2.z += wv.z * xv.z; p2.w += wv.z * xv.w;
    p3.x += wv.w * xv.x; p3.y += wv.w * xv.y; p3.z += wv.w * xv.z; p3.w += wv.w * xv.w;
}

__global__ void __launch_bounds__(512) pool_kernel(const float* __restrict__ x) {
    __shared__ __align__(16) float4 ws[64];
    __shared__ __align__(16) float4 part[4][128][4];

    const int b   = blockIdx.x;
    const int s0  = g_seg_start[b];
    const int s1  = g_seg_start[b + 1];
    const int tid = threadIdx.x;
    const int c   = tid & 127;
    const int r   = tid >> 7;

    float4 p0 = {0,0,0,0}, p1 = {0,0,0,0}, p2 = {0,0,0,0}, p3 = {0,0,0,0};

    for (int n0 = s0; n0 < s1; n0 += 64) {
        int cnt = min(64, s1 - n0);
        __syncthreads();
        if (tid < 64 && tid < cnt) ws[tid] = *(const float4*)(g_weights + (size_t)(n0 + tid) * 4);
        __syncthreads();
        const float* xb = x + (size_t)n0 * DIM + c * 4;
        int i = r;
        for (; i + 28 < cnt; i += 32) {
            float4 x0 = *(const float4*)(xb + (size_t)i * DIM);
            float4 x1 = *(const float4*)(xb + (size_t)(i + 4) * DIM);
            float4 x2 = *(const float4*)(xb + (size_t)(i + 8) * DIM);
            float4 x3 = *(const float4*)(xb + (size_t)(i + 12) * DIM);
            float4 x4 = *(const float4*)(xb + (size_t)(i + 16) * DIM);
            float4 x5 = *(const float4*)(xb + (size_t)(i + 20) * DIM);
            float4 x6 = *(const float4*)(xb + (size_t)(i + 24) * DIM);
            float4 x7 = *(const float4*)(xb + (size_t)(i + 28) * DIM);
            pool_acc(p0, p1, p2, p3, x0, ws[i]);
            pool_acc(p0, p1, p2, p3, x1, ws[i + 4]);
            pool_acc(p0, p1, p2, p3, x2, ws[i + 8]);
            pool_acc(p0, p1, p2, p3, x3, ws[i + 12]);
            pool_acc(p0, p1, p2, p3, x4, ws[i + 16]);
            pool_acc(p0, p1, p2, p3, x5, ws[i + 20]);
            pool_acc(p0, p1, p2, p3, x6, ws[i + 24]);
            pool_acc(p0, p1, p2, p3, x7, ws[i + 28]);
        }
        for (; i < cnt; i += 4) {
            float4 xv = *(const float4*)(xb + (size_t)i * DIM);
            pool_acc(p0, p1, p2, p3, xv, ws[i]);
        }
    }
    __syncthreads();
    part[r][c][0] = p0; part[r][c][1] = p1; part[r][c][2] = p2; part[r][c][3] = p3;
    __syncthreads();

    const int cc = tid & 127;
    const int h  = tid >> 7;
    float4 a = part[0][cc][h], b1 = part[1][cc][h], b2 = part[2][cc][h], b3 = part[3][cc][h];
    float4 o;
    o.x = a.x + b1.x + b2.x + b3.x;
    o.y = a.y + b1.y + b2.y + b3.y;
    o.z = a.z + b1.z + b2.z + b3.z;
    o.w = a.w + b1.w + b2.w + b3.w;
    *(float4*)(g_pooled + (size_t)b * (N_HEADS * DIM) + h * DIM + cc * 4) = o;
}

// ---------------- kernel 5: final GEMM, split-K=4 (tf32 mma.sync) --------------
// 512 CTAs = 16 M-blocks x 8 N-blocks x 4 K-slices; each computes 64x64 over K=512.
#define SPAD 36
#define SKBK 32
#define FG_BM 64
#define FG_BN 64
#define FG_K  2048
#define FG_KSPLIT 4
#define FG_KS (FG_K / FG_KSPLIT)   // 512

__global__ void __launch_bounds__(128) final_gemm_kernel(const float* __restrict__ Wc)
{
    __shared__ __align__(16) unsigned As2[2][FG_BM][SPAD];
    __shared__ __align__(16) unsigned Bs2[2][FG_BN][SPAD];

    const int tid  = threadIdx.x;
    const int lane = tid & 31;
    const int warp = tid >> 5;
    const int wm   = warp >> 1;
    const int wn   = warp & 1;
    const int g    = lane >> 2;
    const int t    = lane & 3;

    const int bm   = (blockIdx.x & 15) * FG_BM;          // 16 M-blocks
    const int bn   = ((blockIdx.x >> 4) & 7) * FG_BN;    // 8 N-blocks
    const int kq   = blockIdx.x >> 7;                    // 4 K-slices
    const int koff = kq * FG_KS;

    int ldRow[4], ldC4[4];
#pragma unroll
    for (int i = 0; i < 4; ++i) { int idx = tid + i * 128; ldRow[i] = idx >> 3; ldC4[i] = idx & 7; }

    float4 pa[4], pb[4];

#define FG_LOAD(kk)                                                                  \
    do {                                                                             \
        _Pragma("unroll")                                                            \
        for (int i = 0; i < 4; ++i) {                                                \
            pa[i] = *(const float4*)(g_pooled + (size_t)(bm + ldRow[i]) * FG_K + (kk) + ldC4[i] * 4); \
            pb[i] = *(const float4*)(Wc       + (size_t)(bn + ldRow[i]) * FG_K + (kk) + ldC4[i] * 4); \
        }                                                                            \
    } while (0)

#define FG_STORE(stage)                                                              \
    do {                                                                             \
        _Pragma("unroll")                                                            \
        for (int i = 0; i < 4; ++i) {                                                \
            uint4 va; va.x = f2tf32(pa[i].x); va.y = f2tf32(pa[i].y);                \
            va.z = f2tf32(pa[i].z); va.w = f2tf32(pa[i].w);                          \
            *(uint4*)&As2[stage][ldRow[i]][ldC4[i] * 4] = va;                        \
            uint4 vb; vb.x = f2tf32(pb[i].x); vb.y = f2tf32(pb[i].y);                \
            vb.z = f2tf32(pb[i].z); vb.w = f2tf32(pb[i].w);                          \
            *(uint4*)&Bs2[stage][ldRow[i]][ldC4[i] * 4] = vb;                        \
        }                                                                            \
    } while (0)

    FG_LOAD(koff);
    FG_STORE(0);
    __syncthreads();

    float acc[2][4][4];
#pragma unroll
    for (int i = 0; i < 2; ++i)
#pragma unroll
        for (int j = 0; j < 4; ++j)
#pragma unroll
            for (int k = 0; k < 4; ++k) acc[i][j][k] = 0.f;

    const int NKT = FG_KS / SKBK;   // 16
    for (int kt = 0; kt < NKT; ++kt) {
        const int s = kt & 1;
        if (kt < NKT - 1) FG_LOAD(koff + (kt + 1) * SKBK);
#pragma unroll
        for (int ks = 0; ks < 4; ++ks) {
            unsigned a[2][4], b[4][2];
#pragma unroll
            for (int mi = 0; mi < 2; ++mi) {
                int r0 = wm * 32 + mi * 16 + g;
                a[mi][0] = As2[s][r0    ][ks * 8 + t];
                a[mi][1] = As2[s][r0 + 8][ks * 8 + t];
                a[mi][2] = As2[s][r0    ][ks * 8 + t + 4];
                a[mi][3] = As2[s][r0 + 8][ks * 8 + t + 4];
            }
#pragma unroll
            for (int ni = 0; ni < 4; ++ni) {
                int c0 = wn * 32 + ni * 8 + g;
                b[ni][0] = Bs2[s][c0][ks * 8 + t];
                b[ni][1] = Bs2[s][c0][ks * 8 + t + 4];
            }
#pragma unroll
            for (int mi = 0; mi < 2; ++mi)
#pragma unroll
                for (int ni = 0; ni < 4; ++ni) {
                    asm volatile(
                        "mma.sync.aligned.m16n8k8.row.col.f32.tf32.tf32.f32 "
                        "{%0,%1,%2,%3}, {%4,%5,%6,%7}, {%8,%9}, {%0,%1,%2,%3};\n"
                        : "+f"(acc[mi][ni][0]), "+f"(acc[mi][ni][1]),
                          "+f"(acc[mi][ni][2]), "+f"(acc[mi][ni][3])
                        : "r"(a[mi][0]), "r"(a[mi][1]), "r"(a[mi][2]), "r"(a[mi][3]),
                          "r"(b[ni][0]), "r"(b[ni][1]));
                }
        }
        if (kt < NKT - 1) {
            FG_STORE(s ^ 1);
            __syncthreads();
        }
    }

    float* outp = g_fgpart[kq];
#pragma unroll
    for (int mi = 0; mi < 2; ++mi)
#pragma unroll
        for (int ni = 0; ni < 4; ++ni) {
            int row0 = bm + wm * 32 + mi * 16 + g;
            int col0 = bn + wn * 32 + ni * 8 + 2 * t;
            outp[(size_t)row0 * 512 + col0]           = acc[mi][ni][0];
            outp[(size_t)row0 * 512 + col0 + 1]       = acc[mi][ni][1];
            outp[(size_t)(row0 + 8) * 512 + col0]     = acc[mi][ni][2];
            outp[(size_t)(row0 + 8) * 512 + col0 + 1] = acc[mi][ni][3];
        }
}

// ---------------- kernel 6: split-K reduce + bias -------------------------------
__global__ void __launch_bounds__(256) fg_reduce_kernel(
    const float* __restrict__ bc, float* __restrict__ out)
{
    int idx4 = blockIdx.x * blockDim.x + threadIdx.x;   // 131072 float4
    float4 p0 = *(const float4*)(g_fgpart[0] + (size_t)idx4 * 4);
    float4 p1 = *(const float4*)(g_fgpart[1] + (size_t)idx4 * 4);
    float4 p2 = *(const float4*)(g_fgpart[2] + (size_t)idx4 * 4);
    float4 p3 = *(const float4*)(g_fgpart[3] + (size_t)idx4 * 4);
    int col = (idx4 * 4) & 511;
    float4 bb = *(const float4*)(bc + col);
    float4 o;
    o.x = p0.x + p1.x + p2.x + p3.x + bb.x;
    o.y = p0.y + p1.y + p2.y + p3.y + bb.y;
    o.z = p0.z + p1.z + p2.z + p3.z + bb.z;
    o.w = p0.w + p1.w + p2.w + p3.w + bb.w;
    *(float4*)(out + (size_t)idx4 * 4) = o;
}

// ---------------- launcher -----------------------------------------------------
extern "C" void kernel_launch(void* const* d_in, const int* in_sizes, int n_in,
                              void* d_out, int out_size) {
    const float* x     = (const float*)d_in[0];
    const int*   batch = (const int*)d_in[1];
    const float* Wh    = (const float*)d_in[2];
    const float* bh    = (const float*)d_in[3];
    const float* ctx   = (const float*)d_in[4];
    const float* Wc    = (const float*)d_in[5];
    const float* bc    = (const float*)d_in[6];
    float*       out   = (float*)d_out;

    cudaFuncSetAttribute(scores_kernel,
                         cudaFuncAttributeMaxDynamicSharedMemorySize, SC_DYN);

    detect_kernel<<<1, 1>>>(batch);
    whconv_kernel<<<128, 256>>>(Wh);
    seg_bounds_kernel<<<N_NODES / 256, 256>>>(batch);
    scores_kernel<<<N_NODES / BM, 256, SC_DYN>>>(x, bh, ctx);   // launch #4: profiled
    softmax_kernel<<<N_SEG, 256>>>();
    pool_kernel<<<N_SEG, 512>>>(x);
    final_gemm_kernel<<<512, 128>>>(Wc);
    fg_reduce_kernel<<<512, 256>>>(bc, out);
}